// round 1
// baseline (speedup 1.0000x reference)
#include <cuda_runtime.h>
#include <math.h>

// ---------------------------------------------------------------------------
// Problem constants
//   x: (T=32, N=16, NT=7, H=32, W=32, C=4)
//   conv stack (all kd=2, 3x3, padHW=1, padD=0):
//     L1: 4->32   (7,32,32) s1 -> (6,32,32)
//     L2: 32->32  (6,32,32) s2 -> (5,16,16)
//     L3: 32->64  (5,16,16) s1 -> (4,16,16)
//     L4: 64->64  (4,16,16) s2 -> (3,8,8)
//     L5: 64->128 (3,8,8)  s1 -> (2,8,8)
//     L6: 128->128(2,8,8)  s2 -> (1,4,4)  => feat (512, 2048)
//   LSTM: HID=512, 32 steps, done-mask reset. FC 512->512 + relu.
// Output: [final_hidden 512*512, hT 16*512, cT 16*512]
// ---------------------------------------------------------------------------

// ---- device scratch arena (no allocations allowed) ----
#define O_S1    0LL
#define SZ_S1   100663296LL      // 512*32*6*32*32
#define O_S2    100663296LL
#define SZ_S2   20971520LL       // 512*32*5*16*16
#define O_S3    121634816LL
#define SZ_S3   33554432LL       // 512*64*4*16*16
#define O_S4    155189248LL
#define SZ_S4   6291456LL        // 512*64*3*8*8
#define O_S5    161480704LL
#define SZ_S5   8388608LL        // 512*128*2*8*8
#define O_FEAT  169869312LL
#define SZ_FEAT 1048576LL        // 512*2048
#define O_XG    170917888LL
#define SZ_XG   1048576LL
#define O_WT1   171966464LL      // 72*32
#define O_WT2   171968768LL      // 576*32
#define O_WT3   171987200LL      // 576*64
#define O_WT4   172024064LL      // 1152*64
#define O_WT5   172097792LL      // 1152*128
#define O_WT6   172245248LL      // 2304*128
#define O_WTIH  172540160LL      // 2048*2048 (permuted gate cols)
#define O_WTHH  176734464LL      // 512*2048  (k-major, permuted gate cols)
#define O_WTF   177783040LL      // 512*512
#define O_BG    178045184LL      // 2048 (b_ih+b_hh, permuted)
#define O_H0    178047232LL      // 16*512
#define O_H1    178055424LL
#define O_C     178063616LL
#define O_HS    178071808LL      // 32*16*512
#define ARENA_TOTAL 178333952LL

__device__ float g_arena[ARENA_TOTAL];

// ---------------------------------------------------------------------------
// Prep kernels (run every launch; tiny)
// ---------------------------------------------------------------------------
__global__ void transpose_rc(const float* __restrict__ src, float* __restrict__ dst,
                             int R, int C, float scale) {
    int i = blockIdx.x * blockDim.x + threadIdx.x;
    if (i < R * C) {
        int r = i / C, c = i % C;
        dst[c * R + r] = src[i] * scale;
    }
}

// W_ih (2048, 2048) -> dst[k*2048 + u*4+g] = W_ih[g*512+u][k]
__global__ void perm_ih(const float* __restrict__ src, float* __restrict__ dst) {
    int i = blockIdx.x * blockDim.x + threadIdx.x;
    if (i < 2048 * 2048) {
        int r = i >> 11, k = i & 2047;
        int g = r >> 9, u = r & 511;
        dst[(k << 11) + (u << 2) + g] = src[i];
    }
}

// W_hh (2048, 512) -> dst[k*2048 + u*4+g] = W_hh[g*512+u][k]
__global__ void perm_hh(const float* __restrict__ src, float* __restrict__ dst) {
    int i = blockIdx.x * blockDim.x + threadIdx.x;
    if (i < 2048 * 512) {
        int r = i >> 9, k = i & 511;
        int g = r >> 9, u = r & 511;
        dst[k * 2048 + (u << 2) + g] = src[i];
    }
}

__global__ void bias_sum(const float* __restrict__ bi, const float* __restrict__ bh,
                         float* __restrict__ dst) {
    int i = blockIdx.x * blockDim.x + threadIdx.x;
    if (i < 2048) {
        int g = i >> 9, u = i & 511;
        dst[(u << 2) + g] = bi[i] + bh[i];
    }
}

// ---------------------------------------------------------------------------
// Implicit-GEMM direct conv.
//   C[m][n], m = ((b*DOUT+od)*HOUT+oh)*WOUT+ow, n = oc, K = CIN*2*9
//   wt is pre-transposed: wt[k*COUT + oc]
//   output NCDHW + bias + relu
// ---------------------------------------------------------------------------
template <int CIN, int COUT, int DIN, int HIN, int WIN, int S, bool XLAYOUT>
__global__ void conv_gemm(const float* __restrict__ in, const float* __restrict__ wt,
                          const float* __restrict__ bias, float* __restrict__ out) {
    constexpr int DOUT = DIN - 1;
    constexpr int HOUT = (S == 1) ? HIN : HIN / 2;
    constexpr int WOUT = (S == 1) ? WIN : WIN / 2;
    constexpr int K = CIN * 18;
    constexpr int BM = 64, BK = 8;
    constexpr int BN = (COUT >= 64) ? 64 : COUT;
    constexpr int THREADS = 16 * (BN / 4);
    constexpr int HW = HOUT * WOUT;
    constexpr int AE = (BM * BK) / THREADS;
    constexpr int BE = (BK * BN) / THREADS;

    __shared__ __align__(16) float As[BK][BM];
    __shared__ __align__(16) float Bs[BK][BN];

    int tid = threadIdx.x;
    int bm0 = blockIdx.x * BM;
    int bn0 = blockIdx.y * BN;

    int a_kl[AE], a_ml[AE], a_b[AE], a_od[AE], a_oh[AE], a_ow[AE];
#pragma unroll
    for (int e = 0; e < AE; e++) {
        int idx = e * THREADS + tid;
        int ml = idx % BM, kl = idx / BM;
        a_ml[e] = ml; a_kl[e] = kl;
        int m = bm0 + ml;
        int ow = m % WOUT; int t1 = m / WOUT;
        int oh = t1 % HOUT; int t2 = t1 / HOUT;
        int od = t2 % DOUT; int b = t2 / DOUT;
        a_b[e] = b; a_od[e] = od; a_oh[e] = oh; a_ow[e] = ow;
    }

    float acc[4][4] = {};
    int tx = tid % (BN / 4);
    int ty = tid / (BN / 4);

    for (int k0 = 0; k0 < K; k0 += BK) {
#pragma unroll
        for (int e = 0; e < AE; e++) {
            int kg = k0 + a_kl[e];
            int cin = kg / 18; int r = kg % 18;
            int kd = r / 9; int r2 = r % 9;
            int kh = r2 / 3; int kw = r2 % 3;
            int ih = a_oh[e] * S - 1 + kh;
            int iw = a_ow[e] * S - 1 + kw;
            int id = a_od[e] + kd;
            float v = 0.f;
            if (ih >= 0 && ih < HIN && iw >= 0 && iw < WIN) {
                int off;
                if (XLAYOUT) {
                    // x layout (B, D, H, W, C) with D=7,H=32,W=32,C=4
                    off = (((a_b[e] * 7 + id) * 32 + ih) * 32 + iw) * 4 + cin;
                } else {
                    off = (((a_b[e] * CIN + cin) * DIN + id) * HIN + ih) * WIN + iw;
                }
                v = in[off];
            }
            As[a_kl[e]][a_ml[e]] = v;
        }
#pragma unroll
        for (int e = 0; e < BE; e++) {
            int idx = e * THREADS + tid;
            int nl = idx % BN, kl = idx / BN;
            Bs[kl][nl] = wt[(k0 + kl) * COUT + bn0 + nl];
        }
        __syncthreads();
#pragma unroll
        for (int kk = 0; kk < BK; kk++) {
            float4 a4 = *(const float4*)&As[kk][ty * 4];
            float4 b4 = *(const float4*)&Bs[kk][tx * 4];
            float av[4] = {a4.x, a4.y, a4.z, a4.w};
            float bv[4] = {b4.x, b4.y, b4.z, b4.w};
#pragma unroll
            for (int i = 0; i < 4; i++)
#pragma unroll
                for (int j = 0; j < 4; j++)
                    acc[i][j] += av[i] * bv[j];
        }
        __syncthreads();
    }

#pragma unroll
    for (int i = 0; i < 4; i++) {
        int m = bm0 + ty * 4 + i;
        int sp = m % HW;
        int t2 = m / HW;            // b*DOUT + od
        int od = t2 % DOUT; int b = t2 / DOUT;
#pragma unroll
        for (int j = 0; j < 4; j++) {
            int n = bn0 + tx * 4 + j;
            float v = acc[i][j] + bias[n];
            v = fmaxf(v, 0.f);
            out[((b * COUT + n) * DOUT + od) * HW + sp] = v;
        }
    }
}

// ---------------------------------------------------------------------------
// Plain tiled SGEMM: C[M][N] = A[M][K] @ Bt[K][N] + bias[n], optional relu.
// BM=BN=64, BK=16, 256 threads, 4x4 register tile. M,N,K multiples of 64/64/16.
// ---------------------------------------------------------------------------
template <bool RELU>
__global__ void gemm_bias(const float* __restrict__ A, const float* __restrict__ Bt,
                          const float* __restrict__ bias, float* __restrict__ C,
                          int M, int N, int K) {
    constexpr int BK = 16;
    __shared__ __align__(16) float As[BK][64];
    __shared__ __align__(16) float Bs[BK][64];
    int tid = threadIdx.x;
    int bm0 = blockIdx.x * 64, bn0 = blockIdx.y * 64;
    int tx = tid % 16, ty = tid / 16;
    float acc[4][4] = {};

    for (int k0 = 0; k0 < K; k0 += BK) {
        {
            int ml = tid >> 2; int kl = (tid & 3) * 4;
            float4 v = *(const float4*)&A[(bm0 + ml) * K + k0 + kl];
            As[kl][ml] = v.x; As[kl + 1][ml] = v.y;
            As[kl + 2][ml] = v.z; As[kl + 3][ml] = v.w;
        }
        {
            int kl = tid >> 4; int nl = (tid & 15) * 4;
            *(float4*)&Bs[kl][nl] = *(const float4*)&Bt[(k0 + kl) * N + bn0 + nl];
        }
        __syncthreads();
#pragma unroll
        for (int kk = 0; kk < BK; kk++) {
            float4 a4 = *(const float4*)&As[kk][ty * 4];
            float4 b4 = *(const float4*)&Bs[kk][tx * 4];
            float av[4] = {a4.x, a4.y, a4.z, a4.w};
            float bv[4] = {b4.x, b4.y, b4.z, b4.w};
#pragma unroll
            for (int i = 0; i < 4; i++)
#pragma unroll
                for (int j = 0; j < 4; j++)
                    acc[i][j] += av[i] * bv[j];
        }
        __syncthreads();
    }
#pragma unroll
    for (int i = 0; i < 4; i++)
#pragma unroll
        for (int j = 0; j < 4; j++) {
            int m = bm0 + ty * 4 + i;
            int n = bn0 + tx * 4 + j;
            float v = acc[i][j] + bias[n];
            if (RELU) v = fmaxf(v, 0.f);
            C[m * N + n] = v;
        }
}

// ---------------------------------------------------------------------------
// One LSTM step.
//   gates[b][u*4+g] = xg[t*16+b][u*4+g] + sum_k h_masked[b][k]*wthh[k][u*4+g]
//   then cell update (block-local: block covers 8 u's = 32 gate cols, all 16 b)
// grid 64 blocks x 128 threads.
// ---------------------------------------------------------------------------
__global__ void lstm_step(const float* __restrict__ xg, const float* __restrict__ wthh,
                          const float* __restrict__ done, const float* __restrict__ h_in,
                          float* __restrict__ h_out, float* __restrict__ c,
                          float* __restrict__ hs, int t) {
    constexpr int PAD = 520;   // 512 + 8 : breaks bank aliasing between b rows
    __shared__ __align__(16) float sh_h[16 * PAD];
    __shared__ __align__(16) float Bs[16][32];

    int tid = threadIdx.x;
    int n0 = blockIdx.x * 32;

    // load h (masked) into padded shared
#pragma unroll
    for (int i = 0; i < 16; i++) {
        int idx4 = i * 128 + tid;        // 2048 float4 total
        int b = idx4 >> 7;               // 128 float4 per batch row
        int q = idx4 & 127;
        float keep = 1.f - done[t * 16 + b];
        float4 v = ((const float4*)h_in)[idx4];
        v.x *= keep; v.y *= keep; v.z *= keep; v.w *= keep;
        ((float4*)sh_h)[b * (PAD / 4) + q] = v;
    }
    __syncthreads();

    int tx = tid & 7;    // gate-col group (8 groups of 4)
    int ty = tid >> 3;   // batch 0..15
    float acc[4] = {0.f, 0.f, 0.f, 0.f};

    for (int k0 = 0; k0 < 512; k0 += 16) {
        {
            int kl = tid >> 3; int nl = (tid & 7) * 4;
            *(float4*)&Bs[kl][nl] = *(const float4*)&wthh[(k0 + kl) * 2048 + n0 + nl];
        }
        __syncthreads();
#pragma unroll
        for (int kk = 0; kk < 16; kk++) {
            float a = sh_h[ty * PAD + k0 + kk];
            float4 b4 = *(const float4*)&Bs[kk][tx * 4];
            acc[0] += a * b4.x; acc[1] += a * b4.y;
            acc[2] += a * b4.z; acc[3] += a * b4.w;
        }
        __syncthreads();
    }

    int b = ty;
    int u = (n0 >> 2) + tx;
    float4 xv = *(const float4*)&xg[(t * 16 + b) * 2048 + n0 + tx * 4];
    float ig = acc[0] + xv.x;
    float fg = acc[1] + xv.y;
    float gg = acc[2] + xv.z;
    float og = acc[3] + xv.w;
    float keep = 1.f - done[t * 16 + b];
    float cold = c[b * 512 + u] * keep;
    float si = 1.f / (1.f + expf(-ig));
    float sf = 1.f / (1.f + expf(-fg));
    float so = 1.f / (1.f + expf(-og));
    float cn = sf * cold + si * tanhf(gg);
    float hn = so * tanhf(cn);
    c[b * 512 + u] = cn;
    h_out[b * 512 + u] = hn;
    hs[(t * 16 + b) * 512 + u] = hn;
}

// ---------------------------------------------------------------------------
extern "C" void kernel_launch(void* const* d_in, const int* in_sizes, int n_in,
                              void* d_out, int out_size) {
    (void)in_sizes; (void)n_in; (void)out_size;
    float* arena = nullptr;
    cudaGetSymbolAddress((void**)&arena, g_arena);

    const float* x    = (const float*)d_in[0];
    const float* done = (const float*)d_in[1];
    const float* h0   = (const float*)d_in[2];
    const float* c0   = (const float*)d_in[3];
    const float* w11  = (const float*)d_in[4];
    const float* b11  = (const float*)d_in[5];
    const float* w12  = (const float*)d_in[6];
    const float* b12  = (const float*)d_in[7];
    const float* w21  = (const float*)d_in[8];
    const float* b21  = (const float*)d_in[9];
    const float* w22  = (const float*)d_in[10];
    const float* b22  = (const float*)d_in[11];
    const float* w31  = (const float*)d_in[12];
    const float* b31  = (const float*)d_in[13];
    const float* w32  = (const float*)d_in[14];
    const float* b32  = (const float*)d_in[15];
    const float* W_ih = (const float*)d_in[16];
    const float* W_hh = (const float*)d_in[17];
    const float* b_ih = (const float*)d_in[18];
    const float* b_hh = (const float*)d_in[19];
    const float* Wf   = (const float*)d_in[20];
    const float* bf   = (const float*)d_in[21];
    float* out = (float*)d_out;

    // ---- prep: weight transposes / permutes ----
    transpose_rc<<<9, 256>>>(w11, arena + O_WT1, 32, 72, 1.f / 255.f);  // fold /255
    transpose_rc<<<72, 256>>>(w12, arena + O_WT2, 32, 576, 1.f);
    transpose_rc<<<144, 256>>>(w21, arena + O_WT3, 64, 576, 1.f);
    transpose_rc<<<288, 256>>>(w22, arena + O_WT4, 64, 1152, 1.f);
    transpose_rc<<<576, 256>>>(w31, arena + O_WT5, 128, 1152, 1.f);
    transpose_rc<<<1152, 256>>>(w32, arena + O_WT6, 128, 2304, 1.f);
    transpose_rc<<<1024, 256>>>(Wf, arena + O_WTF, 512, 512, 1.f);
    perm_ih<<<16384, 256>>>(W_ih, arena + O_WTIH);
    perm_hh<<<4096, 256>>>(W_hh, arena + O_WTHH);
    bias_sum<<<8, 256>>>(b_ih, b_hh, arena + O_BG);
    cudaMemcpyAsync(arena + O_H0, h0, 8192 * sizeof(float), cudaMemcpyDeviceToDevice, 0);
    cudaMemcpyAsync(arena + O_C,  c0, 8192 * sizeof(float), cudaMemcpyDeviceToDevice, 0);

    // ---- conv stack ----
    conv_gemm<4, 32, 7, 32, 32, 1, true><<<dim3(49152, 1), 128>>>(x, arena + O_WT1, b11, arena + O_S1);
    conv_gemm<32, 32, 6, 32, 32, 2, false><<<dim3(10240, 1), 128>>>(arena + O_S1, arena + O_WT2, b12, arena + O_S2);
    conv_gemm<32, 64, 5, 16, 16, 1, false><<<dim3(8192, 1), 256>>>(arena + O_S2, arena + O_WT3, b21, arena + O_S3);
    conv_gemm<64, 64, 4, 16, 16, 2, false><<<dim3(1536, 1), 256>>>(arena + O_S3, arena + O_WT4, b22, arena + O_S4);
    conv_gemm<64, 128, 3, 8, 8, 1, false><<<dim3(1024, 2), 256>>>(arena + O_S4, arena + O_WT5, b31, arena + O_S5);
    conv_gemm<128, 128, 2, 8, 8, 2, false><<<dim3(128, 2), 256>>>(arena + O_S5, arena + O_WT6, b32, arena + O_FEAT);

    // ---- LSTM input-side GEMM (all timesteps at once), bias folded in ----
    gemm_bias<false><<<dim3(8, 32), 256>>>(arena + O_FEAT, arena + O_WTIH, arena + O_BG,
                                           arena + O_XG, 512, 2048, 2048);

    // ---- 32 recurrent steps ----
    for (int t = 0; t < 32; t++) {
        float* hin  = arena + ((t & 1) ? O_H1 : O_H0);
        float* hout = arena + ((t & 1) ? O_H0 : O_H1);
        lstm_step<<<64, 128>>>(arena + O_XG, arena + O_WTHH, done, hin, hout,
                               arena + O_C, arena + O_HS, t);
    }

    // ---- final FC + relu straight into d_out ----
    gemm_bias<true><<<dim3(8, 8), 256>>>(arena + O_HS, arena + O_WTF, bf,
                                         out, 512, 512, 512);

    // ---- hT, cT (final h lives in O_H0 after 32 steps) ----
    cudaMemcpyAsync(out + 262144, arena + O_H0, 8192 * sizeof(float),
                    cudaMemcpyDeviceToDevice, 0);
    cudaMemcpyAsync(out + 270336, arena + O_C, 8192 * sizeof(float),
                    cudaMemcpyDeviceToDevice, 0);
}

// round 2
// speedup vs baseline: 1.0009x; 1.0009x over previous
#include <cuda_runtime.h>
#include <math.h>

// ---------------------------------------------------------------------------
// Problem constants
//   x: (T=32, N=16, NT=7, H=32, W=32, C=4)
//   conv stack (all kd=2, 3x3, padHW=1, padD=0):
//     L1: 4->32   (7,32,32) s1 -> (6,32,32)
//     L2: 32->32  (6,32,32) s2 -> (5,16,16)
//     L3: 32->64  (5,16,16) s1 -> (4,16,16)
//     L4: 64->64  (4,16,16) s2 -> (3,8,8)
//     L5: 64->128 (3,8,8)  s1 -> (2,8,8)
//     L6: 128->128(2,8,8)  s2 -> (1,4,4)  => feat (512, 2048)
//   LSTM: HID=512, 32 steps, done-mask reset. FC 512->512 + relu.
// Output: [final_hidden 512*512, hT 16*512, cT 16*512]
// ---------------------------------------------------------------------------

// ---- device scratch arena (no allocations allowed) ----
#define O_S1    0LL
#define SZ_S1   100663296LL      // 512*32*6*32*32
#define O_S2    100663296LL
#define SZ_S2   20971520LL       // 512*32*5*16*16
#define O_S3    121634816LL
#define SZ_S3   33554432LL       // 512*64*4*16*16
#define O_S4    155189248LL
#define SZ_S4   6291456LL        // 512*64*3*8*8
#define O_S5    161480704LL
#define SZ_S5   8388608LL        // 512*128*2*8*8
#define O_FEAT  169869312LL
#define SZ_FEAT 1048576LL        // 512*2048
#define O_XG    170917888LL
#define SZ_XG   1048576LL
#define O_WT1   171966464LL      // 72*32
#define O_WT2   171968768LL      // 576*32
#define O_WT3   171987200LL      // 576*64
#define O_WT4   172024064LL      // 1152*64
#define O_WT5   172097792LL      // 1152*128
#define O_WT6   172245248LL      // 2304*128
#define O_WTIH  172540160LL      // 2048*2048 (permuted gate cols)
#define O_WTHH  176734464LL      // 512*2048  (k-major, permuted gate cols)
#define O_WTF   177783040LL      // 512*512
#define O_BG    178045184LL      // 2048 (b_ih+b_hh, permuted)
#define O_H0    178047232LL      // 16*512
#define O_H1    178055424LL
#define O_C     178063616LL
#define O_HS    178071808LL      // 32*16*512
#define ARENA_TOTAL 178333952LL

__device__ float g_arena[ARENA_TOTAL];

// ---------------------------------------------------------------------------
// Prep kernels (run every launch; tiny)
// ---------------------------------------------------------------------------
__global__ void transpose_rc(const float* __restrict__ src, float* __restrict__ dst,
                             int R, int C, float scale) {
    int i = blockIdx.x * blockDim.x + threadIdx.x;
    if (i < R * C) {
        int r = i / C, c = i % C;
        dst[c * R + r] = src[i] * scale;
    }
}

// W_ih (2048, 2048) -> dst[k*2048 + u*4+g] = W_ih[g*512+u][k]
__global__ void perm_ih(const float* __restrict__ src, float* __restrict__ dst) {
    int i = blockIdx.x * blockDim.x + threadIdx.x;
    if (i < 2048 * 2048) {
        int r = i >> 11, k = i & 2047;
        int g = r >> 9, u = r & 511;
        dst[(k << 11) + (u << 2) + g] = src[i];
    }
}

// W_hh (2048, 512) -> dst[k*2048 + u*4+g] = W_hh[g*512+u][k]
__global__ void perm_hh(const float* __restrict__ src, float* __restrict__ dst) {
    int i = blockIdx.x * blockDim.x + threadIdx.x;
    if (i < 2048 * 512) {
        int r = i >> 9, k = i & 511;
        int g = r >> 9, u = r & 511;
        dst[k * 2048 + (u << 2) + g] = src[i];
    }
}

__global__ void bias_sum(const float* __restrict__ bi, const float* __restrict__ bh,
                         float* __restrict__ dst) {
    int i = blockIdx.x * blockDim.x + threadIdx.x;
    if (i < 2048) {
        int g = i >> 9, u = i & 511;
        dst[(u << 2) + g] = bi[i] + bh[i];
    }
}

// ---------------------------------------------------------------------------
// Implicit-GEMM direct conv.
//   C[m][n], m = ((b*DOUT+od)*HOUT+oh)*WOUT+ow, n = oc, K = CIN*2*9
//   wt is pre-transposed: wt[k*COUT + oc]
//   output NCDHW + bias + relu
// ---------------------------------------------------------------------------
template <int CIN, int COUT, int DIN, int HIN, int WIN, int S, bool XLAYOUT>
__global__ void conv_gemm(const float* __restrict__ in, const float* __restrict__ wt,
                          const float* __restrict__ bias, float* __restrict__ out) {
    constexpr int DOUT = DIN - 1;
    constexpr int HOUT = (S == 1) ? HIN : HIN / 2;
    constexpr int WOUT = (S == 1) ? WIN : WIN / 2;
    constexpr int K = CIN * 18;
    constexpr int BM = 64, BK = 8;
    constexpr int BN = (COUT >= 64) ? 64 : COUT;
    constexpr int THREADS = 16 * (BN / 4);
    constexpr int HW = HOUT * WOUT;
    constexpr int AE = (BM * BK) / THREADS;
    constexpr int BE = (BK * BN) / THREADS;

    __shared__ __align__(16) float As[BK][BM];
    __shared__ __align__(16) float Bs[BK][BN];

    int tid = threadIdx.x;
    int bm0 = blockIdx.x * BM;
    int bn0 = blockIdx.y * BN;

    int a_kl[AE], a_ml[AE], a_b[AE], a_od[AE], a_oh[AE], a_ow[AE];
#pragma unroll
    for (int e = 0; e < AE; e++) {
        int idx = e * THREADS + tid;
        int ml = idx % BM, kl = idx / BM;
        a_ml[e] = ml; a_kl[e] = kl;
        int m = bm0 + ml;
        int ow = m % WOUT; int t1 = m / WOUT;
        int oh = t1 % HOUT; int t2 = t1 / HOUT;
        int od = t2 % DOUT; int b = t2 / DOUT;
        a_b[e] = b; a_od[e] = od; a_oh[e] = oh; a_ow[e] = ow;
    }

    float acc[4][4] = {};
    int tx = tid % (BN / 4);
    int ty = tid / (BN / 4);

    for (int k0 = 0; k0 < K; k0 += BK) {
#pragma unroll
        for (int e = 0; e < AE; e++) {
            int kg = k0 + a_kl[e];
            int cin = kg / 18; int r = kg % 18;
            int kd = r / 9; int r2 = r % 9;
            int kh = r2 / 3; int kw = r2 % 3;
            int ih = a_oh[e] * S - 1 + kh;
            int iw = a_ow[e] * S - 1 + kw;
            int id = a_od[e] + kd;
            float v = 0.f;
            if (ih >= 0 && ih < HIN && iw >= 0 && iw < WIN) {
                int off;
                if (XLAYOUT) {
                    // x layout (B, D, H, W, C) with D=7,H=32,W=32,C=4
                    off = (((a_b[e] * 7 + id) * 32 + ih) * 32 + iw) * 4 + cin;
                } else {
                    off = (((a_b[e] * CIN + cin) * DIN + id) * HIN + ih) * WIN + iw;
                }
                v = in[off];
            }
            As[a_kl[e]][a_ml[e]] = v;
        }
#pragma unroll
        for (int e = 0; e < BE; e++) {
            int idx = e * THREADS + tid;
            int nl = idx % BN, kl = idx / BN;
            Bs[kl][nl] = wt[(k0 + kl) * COUT + bn0 + nl];
        }
        __syncthreads();
#pragma unroll
        for (int kk = 0; kk < BK; kk++) {
            float4 a4 = *(const float4*)&As[kk][ty * 4];
            float4 b4 = *(const float4*)&Bs[kk][tx * 4];
            float av[4] = {a4.x, a4.y, a4.z, a4.w};
            float bv[4] = {b4.x, b4.y, b4.z, b4.w};
#pragma unroll
            for (int i = 0; i < 4; i++)
#pragma unroll
                for (int j = 0; j < 4; j++)
                    acc[i][j] += av[i] * bv[j];
        }
        __syncthreads();
    }

#pragma unroll
    for (int i = 0; i < 4; i++) {
        int m = bm0 + ty * 4 + i;
        int sp = m % HW;
        int t2 = m / HW;            // b*DOUT + od
        int od = t2 % DOUT; int b = t2 / DOUT;
#pragma unroll
        for (int j = 0; j < 4; j++) {
            int n = bn0 + tx * 4 + j;
            float v = acc[i][j] + bias[n];
            v = fmaxf(v, 0.f);
            out[((b * COUT + n) * DOUT + od) * HW + sp] = v;
        }
    }
}

// ---------------------------------------------------------------------------
// Plain tiled SGEMM: C[M][N] = A[M][K] @ Bt[K][N] + bias[n], optional relu.
// BM=BN=64, BK=16, 256 threads, 4x4 register tile. M,N,K multiples of 64/64/16.
// ---------------------------------------------------------------------------
template <bool RELU>
__global__ void gemm_bias(const float* __restrict__ A, const float* __restrict__ Bt,
                          const float* __restrict__ bias, float* __restrict__ C,
                          int M, int N, int K) {
    constexpr int BK = 16;
    __shared__ __align__(16) float As[BK][64];
    __shared__ __align__(16) float Bs[BK][64];
    int tid = threadIdx.x;
    int bm0 = blockIdx.x * 64, bn0 = blockIdx.y * 64;
    int tx = tid % 16, ty = tid / 16;
    float acc[4][4] = {};

    for (int k0 = 0; k0 < K; k0 += BK) {
        {
            int ml = tid >> 2; int kl = (tid & 3) * 4;
            float4 v = *(const float4*)&A[(bm0 + ml) * K + k0 + kl];
            As[kl][ml] = v.x; As[kl + 1][ml] = v.y;
            As[kl + 2][ml] = v.z; As[kl + 3][ml] = v.w;
        }
        {
            int kl = tid >> 4; int nl = (tid & 15) * 4;
            *(float4*)&Bs[kl][nl] = *(const float4*)&Bt[(k0 + kl) * N + bn0 + nl];
        }
        __syncthreads();
#pragma unroll
        for (int kk = 0; kk < BK; kk++) {
            float4 a4 = *(const float4*)&As[kk][ty * 4];
            float4 b4 = *(const float4*)&Bs[kk][tx * 4];
            float av[4] = {a4.x, a4.y, a4.z, a4.w};
            float bv[4] = {b4.x, b4.y, b4.z, b4.w};
#pragma unroll
            for (int i = 0; i < 4; i++)
#pragma unroll
                for (int j = 0; j < 4; j++)
                    acc[i][j] += av[i] * bv[j];
        }
        __syncthreads();
    }
#pragma unroll
    for (int i = 0; i < 4; i++)
#pragma unroll
        for (int j = 0; j < 4; j++) {
            int m = bm0 + ty * 4 + i;
            int n = bn0 + tx * 4 + j;
            float v = acc[i][j] + bias[n];
            if (RELU) v = fmaxf(v, 0.f);
            C[m * N + n] = v;
        }
}

// ---------------------------------------------------------------------------
// One LSTM step.
//   gates[b][u*4+g] = xg[t*16+b][u*4+g] + sum_k h_masked[b][k]*wthh[k][u*4+g]
//   then cell update (block-local: block covers 8 u's = 32 gate cols, all 16 b)
// grid 64 blocks x 128 threads.
// ---------------------------------------------------------------------------
__global__ void lstm_step(const float* __restrict__ xg, const float* __restrict__ wthh,
                          const float* __restrict__ done, const float* __restrict__ h_in,
                          float* __restrict__ h_out, float* __restrict__ c,
                          float* __restrict__ hs, int t) {
    constexpr int PAD = 520;   // 512 + 8 : breaks bank aliasing between b rows
    __shared__ __align__(16) float sh_h[16 * PAD];
    __shared__ __align__(16) float Bs[16][32];

    int tid = threadIdx.x;
    int n0 = blockIdx.x * 32;

    // load h (masked) into padded shared
#pragma unroll
    for (int i = 0; i < 16; i++) {
        int idx4 = i * 128 + tid;        // 2048 float4 total
        int b = idx4 >> 7;               // 128 float4 per batch row
        int q = idx4 & 127;
        float keep = 1.f - done[t * 16 + b];
        float4 v = ((const float4*)h_in)[idx4];
        v.x *= keep; v.y *= keep; v.z *= keep; v.w *= keep;
        ((float4*)sh_h)[b * (PAD / 4) + q] = v;
    }
    __syncthreads();

    int tx = tid & 7;    // gate-col group (8 groups of 4)
    int ty = tid >> 3;   // batch 0..15
    float acc[4] = {0.f, 0.f, 0.f, 0.f};

    for (int k0 = 0; k0 < 512; k0 += 16) {
        {
            int kl = tid >> 3; int nl = (tid & 7) * 4;
            *(float4*)&Bs[kl][nl] = *(const float4*)&wthh[(k0 + kl) * 2048 + n0 + nl];
        }
        __syncthreads();
#pragma unroll
        for (int kk = 0; kk < 16; kk++) {
            float a = sh_h[ty * PAD + k0 + kk];
            float4 b4 = *(const float4*)&Bs[kk][tx * 4];
            acc[0] += a * b4.x; acc[1] += a * b4.y;
            acc[2] += a * b4.z; acc[3] += a * b4.w;
        }
        __syncthreads();
    }

    int b = ty;
    int u = (n0 >> 2) + tx;
    float4 xv = *(const float4*)&xg[(t * 16 + b) * 2048 + n0 + tx * 4];
    float ig = acc[0] + xv.x;
    float fg = acc[1] + xv.y;
    float gg = acc[2] + xv.z;
    float og = acc[3] + xv.w;
    float keep = 1.f - done[t * 16 + b];
    float cold = c[b * 512 + u] * keep;
    float si = 1.f / (1.f + expf(-ig));
    float sf = 1.f / (1.f + expf(-fg));
    float so = 1.f / (1.f + expf(-og));
    float cn = sf * cold + si * tanhf(gg);
    float hn = so * tanhf(cn);
    c[b * 512 + u] = cn;
    h_out[b * 512 + u] = hn;
    hs[(t * 16 + b) * 512 + u] = hn;
}

// ---------------------------------------------------------------------------
extern "C" void kernel_launch(void* const* d_in, const int* in_sizes, int n_in,
                              void* d_out, int out_size) {
    (void)in_sizes; (void)n_in; (void)out_size;
    float* arena = nullptr;
    cudaGetSymbolAddress((void**)&arena, g_arena);

    const float* x    = (const float*)d_in[0];
    const float* done = (const float*)d_in[1];
    const float* h0   = (const float*)d_in[2];
    const float* c0   = (const float*)d_in[3];
    const float* w11  = (const float*)d_in[4];
    const float* b11  = (const float*)d_in[5];
    const float* w12  = (const float*)d_in[6];
    const float* b12  = (const float*)d_in[7];
    const float* w21  = (const float*)d_in[8];
    const float* b21  = (const float*)d_in[9];
    const float* w22  = (const float*)d_in[10];
    const float* b22  = (const float*)d_in[11];
    const float* w31  = (const float*)d_in[12];
    const float* b31  = (const float*)d_in[13];
    const float* w32  = (const float*)d_in[14];
    const float* b32  = (const float*)d_in[15];
    const float* W_ih = (const float*)d_in[16];
    const float* W_hh = (const float*)d_in[17];
    const float* b_ih = (const float*)d_in[18];
    const float* b_hh = (const float*)d_in[19];
    const float* Wf   = (const float*)d_in[20];
    const float* bf   = (const float*)d_in[21];
    float* out = (float*)d_out;

    // ---- prep: weight transposes / permutes ----
    transpose_rc<<<9, 256>>>(w11, arena + O_WT1, 32, 72, 1.f / 255.f);  // fold /255
    transpose_rc<<<72, 256>>>(w12, arena + O_WT2, 32, 576, 1.f);
    transpose_rc<<<144, 256>>>(w21, arena + O_WT3, 64, 576, 1.f);
    transpose_rc<<<288, 256>>>(w22, arena + O_WT4, 64, 1152, 1.f);
    transpose_rc<<<576, 256>>>(w31, arena + O_WT5, 128, 1152, 1.f);
    transpose_rc<<<1152, 256>>>(w32, arena + O_WT6, 128, 2304, 1.f);
    transpose_rc<<<1024, 256>>>(Wf, arena + O_WTF, 512, 512, 1.f);
    perm_ih<<<16384, 256>>>(W_ih, arena + O_WTIH);
    perm_hh<<<4096, 256>>>(W_hh, arena + O_WTHH);
    bias_sum<<<8, 256>>>(b_ih, b_hh, arena + O_BG);
    cudaMemcpyAsync(arena + O_H0, h0, 8192 * sizeof(float), cudaMemcpyDeviceToDevice, 0);
    cudaMemcpyAsync(arena + O_C,  c0, 8192 * sizeof(float), cudaMemcpyDeviceToDevice, 0);

    // ---- conv stack ----
    conv_gemm<4, 32, 7, 32, 32, 1, true><<<dim3(49152, 1), 128>>>(x, arena + O_WT1, b11, arena + O_S1);
    conv_gemm<32, 32, 6, 32, 32, 2, false><<<dim3(10240, 1), 128>>>(arena + O_S1, arena + O_WT2, b12, arena + O_S2);
    conv_gemm<32, 64, 5, 16, 16, 1, false><<<dim3(8192, 1), 256>>>(arena + O_S2, arena + O_WT3, b21, arena + O_S3);
    conv_gemm<64, 64, 4, 16, 16, 2, false><<<dim3(1536, 1), 256>>>(arena + O_S3, arena + O_WT4, b22, arena + O_S4);
    conv_gemm<64, 128, 3, 8, 8, 1, false><<<dim3(1024, 2), 256>>>(arena + O_S4, arena + O_WT5, b31, arena + O_S5);
    conv_gemm<128, 128, 2, 8, 8, 2, false><<<dim3(128, 2), 256>>>(arena + O_S5, arena + O_WT6, b32, arena + O_FEAT);

    // ---- LSTM input-side GEMM (all timesteps at once), bias folded in ----
    gemm_bias<false><<<dim3(8, 32), 256>>>(arena + O_FEAT, arena + O_WTIH, arena + O_BG,
                                           arena + O_XG, 512, 2048, 2048);

    // ---- 32 recurrent steps ----
    for (int t = 0; t < 32; t++) {
        float* hin  = arena + ((t & 1) ? O_H1 : O_H0);
        float* hout = arena + ((t & 1) ? O_H0 : O_H1);
        lstm_step<<<64, 128>>>(arena + O_XG, arena + O_WTHH, done, hin, hout,
                               arena + O_C, arena + O_HS, t);
    }

    // ---- final FC + relu straight into d_out ----
    gemm_bias<true><<<dim3(8, 8), 256>>>(arena + O_HS, arena + O_WTF, bf,
                                         out, 512, 512, 512);

    // ---- hT, cT (final h lives in O_H0 after 32 steps) ----
    cudaMemcpyAsync(out + 262144, arena + O_H0, 8192 * sizeof(float),
                    cudaMemcpyDeviceToDevice, 0);
    cudaMemcpyAsync(out + 270336, arena + O_C, 8192 * sizeof(float),
                    cudaMemcpyDeviceToDevice, 0);
}

// round 4
// speedup vs baseline: 1.7103x; 1.7087x over previous
#include <cuda_runtime.h>
#include <cuda_bf16.h>
#include <mma.h>
#include <math.h>
#include <stdint.h>

using namespace nvcuda;

// ============================================================================
// CNN(6x conv3d) + LSTM(32) + FC.  Tensor path: wmma bf16 (3-term hi/lo split),
// fp32 accumulate.  Activations NDHWC as bf16 hi/lo pairs.  Weights k-major.
// ============================================================================

__device__ __forceinline__ void split2(float a, float b, uint32_t& ph, uint32_t& pl) {
    __nv_bfloat162 h, l;
    h.x = __float2bfloat16_rn(a); h.y = __float2bfloat16_rn(b);
    l.x = __float2bfloat16_rn(a - __bfloat162float(h.x));
    l.y = __float2bfloat16_rn(b - __bfloat162float(h.y));
    ph = *reinterpret_cast<uint32_t*>(&h);
    pl = *reinterpret_cast<uint32_t*>(&l);
}

// ---- bf16 arena ----
#define O_A1H 0LL
#define O_A1L 100663296LL
#define O_A2H 201326592LL
#define O_A2L 222298112LL
#define O_A3H 243269632LL
#define O_A3L 276824064LL
#define O_A4H 310378496LL
#define O_A4L 316669952LL
#define O_A5H 322961408LL
#define O_A5L 331350016LL
#define O_FH  339738624LL
#define O_FL  340787200LL
#define O_W1H 341835776LL
#define O_W1L 341839872LL
#define O_W2H 341843968LL
#define O_W2L 341862400LL
#define O_W3H 341880832LL
#define O_W3L 341917696LL
#define O_W4H 341954560LL
#define O_W4L 342028288LL
#define O_W5H 342102016LL
#define O_W5L 342249472LL
#define O_W6H 342396928LL
#define O_W6L 342691840LL
#define O_WIHH 342986752LL
#define O_WIHL 347181056LL
#define O_WFH 351375360LL
#define O_WFL 351637504LL
#define BH_TOTAL 351899648LL
__device__ __nv_bfloat16 g_bh[BH_TOTAL];

// ---- fp32 arena ----
#define F_XG   0LL
#define F_WTHH 1048576LL
#define F_BG   2097152LL
#define F_H0   2099200LL
#define F_H1   2107392LL
#define F_C    2115584LL
#define F_HS   2123776LL
#define F_TOTAL 2385920LL
__device__ float g_f[F_TOTAL];

// ---- prep kernels (k-major weight layouts) ----
__global__ void convw_prep(const float* __restrict__ src, __nv_bfloat16* __restrict__ dh,
                           __nv_bfloat16* __restrict__ dl, int CIN, int COUT, int Kpad, float scale) {
    int i = blockIdx.x * blockDim.x + threadIdx.x;
    if (i >= COUT * Kpad) return;
    int co = i / Kpad, kk = i % Kpad;
    float v = 0.f;
    if (kk < CIN * 18) {
        int cin = kk % CIN, tap = kk / CIN;
        v = src[(co * CIN + cin) * 18 + tap] * scale;
    }
    __nv_bfloat16 h = __float2bfloat16_rn(v);
    long o = (long)kk * COUT + co;      // k-major
    dh[o] = h;
    dl[o] = __float2bfloat16_rn(v - __bfloat162float(h));
}
__global__ void ihw_prep(const float* __restrict__ src, __nv_bfloat16* __restrict__ dh,
                         __nv_bfloat16* __restrict__ dl) {
    int i = blockIdx.x * blockDim.x + threadIdx.x;
    if (i >= 2048 * 2048) return;
    int r = i >> 11, k = i & 2047;
    int g = r >> 9, u = r & 511;
    int n2 = (u << 2) + g;
    int k2 = ((k & 15) << 7) + (k >> 4);   // ref k=(c*16+sp) -> mine (sp*128+c)
    float v = src[i];
    __nv_bfloat16 h = __float2bfloat16_rn(v);
    long o = (long)k2 * 2048 + n2;          // k-major
    dh[o] = h;
    dl[o] = __float2bfloat16_rn(v - __bfloat162float(h));
}
__global__ void wf_prep(const float* __restrict__ src, __nv_bfloat16* __restrict__ dh,
                        __nv_bfloat16* __restrict__ dl) {
    int i = blockIdx.x * blockDim.x + threadIdx.x;
    if (i >= 512 * 512) return;
    int n = i >> 9, k = i & 511;
    float v = src[i];
    __nv_bfloat16 h = __float2bfloat16_rn(v);
    long o = (long)k * 512 + n;             // k-major
    dh[o] = h;
    dl[o] = __float2bfloat16_rn(v - __bfloat162float(h));
}
__global__ void perm_hh(const float* __restrict__ src, float* __restrict__ dst) {
    int i = blockIdx.x * blockDim.x + threadIdx.x;
    if (i < 2048 * 512) {
        int r = i >> 9, k = i & 511;
        int g = r >> 9, u = r & 511;
        dst[k * 2048 + (u << 2) + g] = src[i];
    }
}
__global__ void bias_sum(const float* __restrict__ bi, const float* __restrict__ bh2,
                         float* __restrict__ dst) {
    int i = blockIdx.x * blockDim.x + threadIdx.x;
    if (i < 2048) {
        int g = i >> 9, u = i & 511;
        dst[(u << 2) + g] = bi[i] + bh2[i];
    }
}

// ============================================================================
// wmma implicit-GEMM conv.  CTA tile: 128 x BN, BK=16.  8 warps.
//   m = NDHWC flat output index, n = out channel, K = tap*CIN + cin.
// ============================================================================
template <int CIN, int COUT, int DIN, int HIN, int WIN, int S, bool FIRST>
__global__ __launch_bounds__(256) void conv_wm(
    const float* __restrict__ xin,
    const __nv_bfloat16* __restrict__ ahi, const __nv_bfloat16* __restrict__ alo,
    const __nv_bfloat16* __restrict__ whi, const __nv_bfloat16* __restrict__ wlo,
    const float* __restrict__ bias,
    __nv_bfloat16* __restrict__ ohi, __nv_bfloat16* __restrict__ olo) {
    constexpr int DOUT = DIN - 1;
    constexpr int HOUT = (S == 1) ? HIN : HIN / 2;
    constexpr int WOUT = (S == 1) ? WIN : WIN / 2;
    constexpr int Kpad = (CIN == 4) ? 80 : CIN * 18;
    constexpr int BN = (COUT >= 64) ? 64 : COUT;
    constexpr int L2C = (CIN == 32) ? 5 : (CIN == 64) ? 6 : 7;
    constexpr int LDA = 24;            // bf16 elems per As row (pad 16->24)
    constexpr int LDB = BN + 8;
    constexpr int LDC = BN + 4;
    constexpr int WN = (BN == 64) ? 2 : 1;   // warps along n
    constexpr int MF = (BN == 64) ? 2 : 1;   // m-frags per warp
    constexpr int SZ_LOAD = 2 * 128 * LDA * 2 + 2 * 16 * LDB * 2;
    constexpr int SZ_C = 128 * LDC * 4;
    constexpr int SMSZ = (SZ_LOAD > SZ_C) ? SZ_LOAD : SZ_C;

    __shared__ __align__(32) char sm[SMSZ];
    __nv_bfloat16* AsH = (__nv_bfloat16*)sm;
    __nv_bfloat16* AsL = AsH + 128 * LDA;
    __nv_bfloat16* BsH = AsL + 128 * LDA;
    __nv_bfloat16* BsL = BsH + 16 * LDB;
    float* Cs = (float*)sm;

    int tid = threadIdx.x, wid = tid >> 5;
    int m0 = blockIdx.x * 128;
    int n0 = blockIdx.y * BN;

    // per-thread A row (2 threads/row, halves of k)
    int r = tid >> 1, h8 = (tid & 1) * 8;
    int m = m0 + r;
    int ow = m % WOUT; int t1 = m / WOUT;
    int oh = t1 % HOUT; int t2 = t1 / HOUT;
    int od = t2 % DOUT; int bb = t2 / DOUT;

    int wm = wid / WN, wn = wid % WN;
    wmma::fragment<wmma::accumulator, 16, 16, 16, float> acc[MF][2];
#pragma unroll
    for (int i = 0; i < MF; i++)
#pragma unroll
        for (int j = 0; j < 2; j++) wmma::fill_fragment(acc[i][j], 0.f);

    for (int k0 = 0; k0 < Kpad; k0 += 16) {
        __syncthreads();
        // ---- A gather ----
        if (FIRST) {   // CIN == 4: two taps of 4 channels each
#pragma unroll
            for (int j = 0; j < 2; j++) {
                int kj = k0 + h8 + j * 4;
                int tap = kj >> 2;
                uint2 vh = make_uint2(0u, 0u), vl = make_uint2(0u, 0u);
                if (tap < 18) {
                    int kd = (tap >= 9) ? 1 : 0;
                    int r2 = tap - 9 * kd;
                    int kh = r2 / 3, kw = r2 - 3 * kh;
                    int ih = oh - 1 + kh, iw = ow - 1 + kw;
                    if ((unsigned)ih < (unsigned)HIN && (unsigned)iw < (unsigned)WIN) {
                        int id = od + kd;
                        float4 v = *(const float4*)(xin + ((((long)bb * DIN + id) * HIN + ih) * WIN + iw) * 4);
                        split2(v.x, v.y, vh.x, vl.x);
                        split2(v.z, v.w, vh.y, vl.y);
                    }
                }
                *(uint2*)(AsH + r * LDA + h8 + j * 4) = vh;
                *(uint2*)(AsL + r * LDA + h8 + j * 4) = vl;
            }
        } else {       // CIN >= 32: 8 contiguous channels within one tap
            int kk = k0 + h8;
            int tap = kk >> L2C;
            int cin = kk & (CIN - 1);
            int kd = (tap >= 9) ? 1 : 0;
            int r2 = tap - 9 * kd;
            int kh = r2 / 3, kw = r2 - 3 * kh;
            int ih = oh * S - 1 + kh, iw = ow * S - 1 + kw;
            uint4 vh = make_uint4(0u, 0u, 0u, 0u), vl = make_uint4(0u, 0u, 0u, 0u);
            if ((unsigned)ih < (unsigned)HIN && (unsigned)iw < (unsigned)WIN) {
                int id = od + kd;
                long off = ((((long)bb * DIN + id) * HIN + ih) * WIN + iw) * CIN + cin;
                vh = *(const uint4*)(ahi + off);
                vl = *(const uint4*)(alo + off);
            }
            *(uint4*)(AsH + r * LDA + h8) = vh;
            *(uint4*)(AsL + r * LDA + h8) = vl;
        }
        // ---- B load (k-major, contiguous) ----
        if (BN == 64) {
            int e = tid * 4;
            int kb = e >> 6, nb = e & 63;
            long go = (long)(k0 + kb) * COUT + n0 + nb;
            *(uint2*)(BsH + kb * LDB + nb) = *(const uint2*)(whi + go);
            *(uint2*)(BsL + kb * LDB + nb) = *(const uint2*)(wlo + go);
        } else {
            int e = tid * 2;
            int kb = e >> 5, nb = e & 31;
            long go = (long)(k0 + kb) * COUT + n0 + nb;
            *(uint32_t*)(BsH + kb * LDB + nb) = *(const uint32_t*)(whi + go);
            *(uint32_t*)(BsL + kb * LDB + nb) = *(const uint32_t*)(wlo + go);
        }
        __syncthreads();
        // ---- wmma ----
        wmma::fragment<wmma::matrix_a, 16, 16, 16, __nv_bfloat16, wmma::row_major> fah[MF], fal[MF];
        wmma::fragment<wmma::matrix_b, 16, 16, 16, __nv_bfloat16, wmma::row_major> fbh[2], fbl[2];
#pragma unroll
        for (int i = 0; i < MF; i++) {
            wmma::load_matrix_sync(fah[i], AsH + (wm * MF * 16 + i * 16) * LDA, LDA);
            wmma::load_matrix_sync(fal[i], AsL + (wm * MF * 16 + i * 16) * LDA, LDA);
        }
#pragma unroll
        for (int j = 0; j < 2; j++) {
            wmma::load_matrix_sync(fbh[j], BsH + wn * 32 + j * 16, LDB);
            wmma::load_matrix_sync(fbl[j], BsL + wn * 32 + j * 16, LDB);
        }
#pragma unroll
        for (int i = 0; i < MF; i++)
#pragma unroll
            for (int j = 0; j < 2; j++) {
                wmma::mma_sync(acc[i][j], fah[i], fbh[j], acc[i][j]);
                wmma::mma_sync(acc[i][j], fah[i], fbl[j], acc[i][j]);
                wmma::mma_sync(acc[i][j], fal[i], fbh[j], acc[i][j]);
            }
    }
    __syncthreads();
#pragma unroll
    for (int i = 0; i < MF; i++)
#pragma unroll
        for (int j = 0; j < 2; j++)
            wmma::store_matrix_sync(Cs + (wm * MF * 16 + i * 16) * LDC + wn * 32 + j * 16,
                                    acc[i][j], LDC, wmma::mem_row_major);
    __syncthreads();
    // ---- epilogue: bias + relu + split -> NDHWC hi/lo ----
    {
        int r2 = tid >> 1, ch0 = (tid & 1) * (BN / 2);
        long base = (long)(m0 + r2) * COUT + n0 + ch0;
#pragma unroll
        for (int c = 0; c < BN / 2; c += 4) {
            float v0 = Cs[r2 * LDC + ch0 + c]     + bias[n0 + ch0 + c];
            float v1 = Cs[r2 * LDC + ch0 + c + 1] + bias[n0 + ch0 + c + 1];
            float v2 = Cs[r2 * LDC + ch0 + c + 2] + bias[n0 + ch0 + c + 2];
            float v3 = Cs[r2 * LDC + ch0 + c + 3] + bias[n0 + ch0 + c + 3];
            v0 = fmaxf(v0, 0.f); v1 = fmaxf(v1, 0.f);
            v2 = fmaxf(v2, 0.f); v3 = fmaxf(v3, 0.f);
            uint2 ph, pl;
            split2(v0, v1, ph.x, pl.x);
            split2(v2, v3, ph.y, pl.y);
            *(uint2*)(ohi + base + c) = ph;
            *(uint2*)(olo + base + c) = pl;
        }
    }
}

// ============================================================================
// wmma plain GEMM, fp32 out: C[M x NTOT] = A[M x K] @ W(k-major) + bias.
// CTA tile 128 x 64.
// ============================================================================
template <int NTOT, int K, bool ASPLIT, bool RELU>
__global__ __launch_bounds__(256) void mm_wm(
    const float* __restrict__ afp,
    const __nv_bfloat16* __restrict__ ahi, const __nv_bfloat16* __restrict__ alo,
    const __nv_bfloat16* __restrict__ whi, const __nv_bfloat16* __restrict__ wlo,
    const float* __restrict__ bias, float* __restrict__ out) {
    constexpr int LDA = 24, LDB = 72, LDC = 68;
    constexpr int SZ_LOAD = 2 * 128 * LDA * 2 + 2 * 16 * LDB * 2;
    constexpr int SZ_C = 128 * LDC * 4;
    constexpr int SMSZ = (SZ_LOAD > SZ_C) ? SZ_LOAD : SZ_C;

    __shared__ __align__(32) char sm[SMSZ];
    __nv_bfloat16* AsH = (__nv_bfloat16*)sm;
    __nv_bfloat16* AsL = AsH + 128 * LDA;
    __nv_bfloat16* BsH = AsL + 128 * LDA;
    __nv_bfloat16* BsL = BsH + 16 * LDB;
    float* Cs = (float*)sm;

    int tid = threadIdx.x, wid = tid >> 5;
    int m0 = blockIdx.x * 128;
    int n0 = blockIdx.y * 64;
    int r = tid >> 1, h8 = (tid & 1) * 8;
    long mrow = m0 + r;
    int wm = wid >> 1, wn = wid & 1;

    wmma::fragment<wmma::accumulator, 16, 16, 16, float> acc[2][2];
#pragma unroll
    for (int i = 0; i < 2; i++)
#pragma unroll
        for (int j = 0; j < 2; j++) wmma::fill_fragment(acc[i][j], 0.f);

    for (int k0 = 0; k0 < K; k0 += 16) {
        __syncthreads();
        if (ASPLIT) {
            float4 v0 = *(const float4*)(afp + mrow * K + k0 + h8);
            float4 v1 = *(const float4*)(afp + mrow * K + k0 + h8 + 4);
            uint4 vh, vl;
            split2(v0.x, v0.y, vh.x, vl.x);
            split2(v0.z, v0.w, vh.y, vl.y);
            split2(v1.x, v1.y, vh.z, vl.z);
            split2(v1.z, v1.w, vh.w, vl.w);
            *(uint4*)(AsH + r * LDA + h8) = vh;
            *(uint4*)(AsL + r * LDA + h8) = vl;
        } else {
            long off = mrow * K + k0 + h8;
            *(uint4*)(AsH + r * LDA + h8) = *(const uint4*)(ahi + off);
            *(uint4*)(AsL + r * LDA + h8) = *(const uint4*)(alo + off);
        }
        {
            int e = tid * 4;
            int kb = e >> 6, nb = e & 63;
            long go = (long)(k0 + kb) * NTOT + n0 + nb;
            *(uint2*)(BsH + kb * LDB + nb) = *(const uint2*)(whi + go);
            *(uint2*)(BsL + kb * LDB + nb) = *(const uint2*)(wlo + go);
        }
        __syncthreads();
        wmma::fragment<wmma::matrix_a, 16, 16, 16, __nv_bfloat16, wmma::row_major> fah[2], fal[2];
        wmma::fragment<wmma::matrix_b, 16, 16, 16, __nv_bfloat16, wmma::row_major> fbh[2], fbl[2];
#pragma unroll
        for (int i = 0; i < 2; i++) {
            wmma::load_matrix_sync(fah[i], AsH + (wm * 32 + i * 16) * LDA, LDA);
            wmma::load_matrix_sync(fal[i], AsL + (wm * 32 + i * 16) * LDA, LDA);
        }
#pragma unroll
        for (int j = 0; j < 2; j++) {
            wmma::load_matrix_sync(fbh[j], BsH + wn * 32 + j * 16, LDB);
            wmma::load_matrix_sync(fbl[j], BsL + wn * 32 + j * 16, LDB);
        }
#pragma unroll
        for (int i = 0; i < 2; i++)
#pragma unroll
            for (int j = 0; j < 2; j++) {
                wmma::mma_sync(acc[i][j], fah[i], fbh[j], acc[i][j]);
                wmma::mma_sync(acc[i][j], fah[i], fbl[j], acc[i][j]);
                wmma::mma_sync(acc[i][j], fal[i], fbh[j], acc[i][j]);
            }
    }
    __syncthreads();
#pragma unroll
    for (int i = 0; i < 2; i++)
#pragma unroll
        for (int j = 0; j < 2; j++)
            wmma::store_matrix_sync(Cs + (wm * 32 + i * 16) * LDC + wn * 32 + j * 16,
                                    acc[i][j], LDC, wmma::mem_row_major);
    __syncthreads();
    {
        int r2 = tid >> 1, ch0 = (tid & 1) * 32;
        long base = (long)(m0 + r2) * NTOT + n0 + ch0;
#pragma unroll
        for (int c = 0; c < 32; c += 4) {
            float4 v;
            v.x = Cs[r2 * LDC + ch0 + c]     + bias[n0 + ch0 + c];
            v.y = Cs[r2 * LDC + ch0 + c + 1] + bias[n0 + ch0 + c + 1];
            v.z = Cs[r2 * LDC + ch0 + c + 2] + bias[n0 + ch0 + c + 2];
            v.w = Cs[r2 * LDC + ch0 + c + 3] + bias[n0 + ch0 + c + 3];
            if (RELU) {
                v.x = fmaxf(v.x, 0.f); v.y = fmaxf(v.y, 0.f);
                v.z = fmaxf(v.z, 0.f); v.w = fmaxf(v.w, 0.f);
            }
            *(float4*)(out + base + c) = v;
        }
    }
}

// ---- LSTM recurrent step (fp32, validated) ----
__global__ void lstm_step(const float* __restrict__ xg, const float* __restrict__ wthh,
                          const float* __restrict__ done, const float* __restrict__ h_in,
                          float* __restrict__ h_out, float* __restrict__ c,
                          float* __restrict__ hs, int t) {
    constexpr int PAD = 520;
    __shared__ __align__(16) float sh_h[16 * PAD];
    __shared__ __align__(16) float Bs[16][32];
    int tid = threadIdx.x;
    int n0 = blockIdx.x * 32;
#pragma unroll
    for (int i = 0; i < 16; i++) {
        int idx4 = i * 128 + tid;
        int b = idx4 >> 7;
        int qq = idx4 & 127;
        float keep = 1.f - done[t * 16 + b];
        float4 v = ((const float4*)h_in)[idx4];
        v.x *= keep; v.y *= keep; v.z *= keep; v.w *= keep;
        ((float4*)sh_h)[b * (PAD / 4) + qq] = v;
    }
    __syncthreads();
    int tx = tid & 7, ty = tid >> 3;
    float acc[4] = {0.f, 0.f, 0.f, 0.f};
    for (int k0 = 0; k0 < 512; k0 += 16) {
        {
            int kl = tid >> 3, nl = (tid & 7) * 4;
            *(float4*)&Bs[kl][nl] = *(const float4*)&wthh[(k0 + kl) * 2048 + n0 + nl];
        }
        __syncthreads();
#pragma unroll
        for (int kk = 0; kk < 16; kk++) {
            float a = sh_h[ty * PAD + k0 + kk];
            float4 b4 = *(const float4*)&Bs[kk][tx * 4];
            acc[0] += a * b4.x; acc[1] += a * b4.y;
            acc[2] += a * b4.z; acc[3] += a * b4.w;
        }
        __syncthreads();
    }
    int b = ty;
    int u = (n0 >> 2) + tx;
    float4 xv = *(const float4*)&xg[(t * 16 + b) * 2048 + n0 + tx * 4];
    float ig = acc[0] + xv.x, fg = acc[1] + xv.y, gg = acc[2] + xv.z, og = acc[3] + xv.w;
    float keep = 1.f - done[t * 16 + b];
    float cold = c[b * 512 + u] * keep;
    float si = 1.f / (1.f + expf(-ig));
    float sf = 1.f / (1.f + expf(-fg));
    float so = 1.f / (1.f + expf(-og));
    float cn = sf * cold + si * tanhf(gg);
    float hn = so * tanhf(cn);
    c[b * 512 + u] = cn;
    h_out[b * 512 + u] = hn;
    hs[(t * 16 + b) * 512 + u] = hn;
}

// ---------------------------------------------------------------------------
extern "C" void kernel_launch(void* const* d_in, const int* in_sizes, int n_in,
                              void* d_out, int out_size) {
    (void)in_sizes; (void)n_in; (void)out_size;
    __nv_bfloat16* bh = nullptr;
    float* fa = nullptr;
    cudaGetSymbolAddress((void**)&bh, g_bh);
    cudaGetSymbolAddress((void**)&fa, g_f);

    const float* x    = (const float*)d_in[0];
    const float* done = (const float*)d_in[1];
    const float* h0   = (const float*)d_in[2];
    const float* c0   = (const float*)d_in[3];
    const float* w11  = (const float*)d_in[4];
    const float* b11  = (const float*)d_in[5];
    const float* w12  = (const float*)d_in[6];
    const float* b12  = (const float*)d_in[7];
    const float* w21  = (const float*)d_in[8];
    const float* b21  = (const float*)d_in[9];
    const float* w22  = (const float*)d_in[10];
    const float* b22  = (const float*)d_in[11];
    const float* w31  = (const float*)d_in[12];
    const float* b31  = (const float*)d_in[13];
    const float* w32  = (const float*)d_in[14];
    const float* b32  = (const float*)d_in[15];
    const float* W_ih = (const float*)d_in[16];
    const float* W_hh = (const float*)d_in[17];
    const float* b_ih = (const float*)d_in[18];
    const float* b_hh = (const float*)d_in[19];
    const float* Wf   = (const float*)d_in[20];
    const float* bf   = (const float*)d_in[21];
    float* out = (float*)d_out;

    // ---- weight prep ----
    convw_prep<<<16, 256>>>(w11, bh + O_W1H, bh + O_W1L, 4, 32, 80, 1.f / 255.f);
    convw_prep<<<72, 256>>>(w12, bh + O_W2H, bh + O_W2L, 32, 32, 576, 1.f);
    convw_prep<<<144, 256>>>(w21, bh + O_W3H, bh + O_W3L, 32, 64, 576, 1.f);
    convw_prep<<<288, 256>>>(w22, bh + O_W4H, bh + O_W4L, 64, 64, 1152, 1.f);
    convw_prep<<<576, 256>>>(w31, bh + O_W5H, bh + O_W5L, 64, 128, 1152, 1.f);
    convw_prep<<<1152, 256>>>(w32, bh + O_W6H, bh + O_W6L, 128, 128, 2304, 1.f);
    ihw_prep<<<16384, 256>>>(W_ih, bh + O_WIHH, bh + O_WIHL);
    wf_prep<<<1024, 256>>>(Wf, bh + O_WFH, bh + O_WFL);
    perm_hh<<<4096, 256>>>(W_hh, fa + F_WTHH);
    bias_sum<<<8, 256>>>(b_ih, b_hh, fa + F_BG);
    cudaMemcpyAsync(fa + F_H0, h0, 8192 * sizeof(float), cudaMemcpyDeviceToDevice, 0);
    cudaMemcpyAsync(fa + F_C,  c0, 8192 * sizeof(float), cudaMemcpyDeviceToDevice, 0);

    // ---- conv stack (wmma bf16) ----
    conv_wm<4, 32, 7, 32, 32, 1, true><<<dim3(24576, 1), 256>>>(
        x, nullptr, nullptr, bh + O_W1H, bh + O_W1L, b11, bh + O_A1H, bh + O_A1L);
    conv_wm<32, 32, 6, 32, 32, 2, false><<<dim3(5120, 1), 256>>>(
        nullptr, bh + O_A1H, bh + O_A1L, bh + O_W2H, bh + O_W2L, b12, bh + O_A2H, bh + O_A2L);
    conv_wm<32, 64, 5, 16, 16, 1, false><<<dim3(4096, 1), 256>>>(
        nullptr, bh + O_A2H, bh + O_A2L, bh + O_W3H, bh + O_W3L, b21, bh + O_A3H, bh + O_A3L);
    conv_wm<64, 64, 4, 16, 16, 2, false><<<dim3(768, 1), 256>>>(
        nullptr, bh + O_A3H, bh + O_A3L, bh + O_W4H, bh + O_W4L, b22, bh + O_A4H, bh + O_A4L);
    conv_wm<64, 128, 3, 8, 8, 1, false><<<dim3(512, 2), 256>>>(
        nullptr, bh + O_A4H, bh + O_A4L, bh + O_W5H, bh + O_W5L, b31, bh + O_A5H, bh + O_A5L);
    conv_wm<128, 128, 2, 8, 8, 2, false><<<dim3(64, 2), 256>>>(
        nullptr, bh + O_A5H, bh + O_A5L, bh + O_W6H, bh + O_W6L, b32, bh + O_FH, bh + O_FL);

    // ---- LSTM input GEMM (512 x 2048 x 2048) ----
    mm_wm<2048, 2048, false, false><<<dim3(4, 32), 256>>>(
        nullptr, bh + O_FH, bh + O_FL, bh + O_WIHH, bh + O_WIHL, fa + F_BG, fa + F_XG);

    // ---- 32 recurrent steps ----
    for (int t = 0; t < 32; t++) {
        float* hin  = fa + ((t & 1) ? F_H1 : F_H0);
        float* hout = fa + ((t & 1) ? F_H0 : F_H1);
        lstm_step<<<64, 128>>>(fa + F_XG, fa + F_WTHH, done, hin, hout,
                               fa + F_C, fa + F_HS, t);
    }

    // ---- final FC + relu into d_out ----
    mm_wm<512, 512, true, true><<<dim3(4, 8), 256>>>(
        fa + F_HS, nullptr, nullptr, bh + O_WFH, bh + O_WFL, bf, out);

    // ---- hT, cT ----
    cudaMemcpyAsync(out + 262144, fa + F_H0, 8192 * sizeof(float),
                    cudaMemcpyDeviceToDevice, 0);
    cudaMemcpyAsync(out + 270336, fa + F_C, 8192 * sizeof(float),
                    cudaMemcpyDeviceToDevice, 0);
}